// round 15
// baseline (speedup 1.0000x reference)
#include <cuda_runtime.h>
#include <cuda_fp16.h>
#include <cstdint>

#define N_ROWS  262144
#define IN_DIM  512
#define OUT_DIM 128
#define TILE_M  64
#define GEMM_BLOCKS (N_ROWS / TILE_M)   // 4096
#define CMP_BLOCKS  512
#define FIX_SCALE 1048576.0             // 2^20

// ---------------- device scratch (no allocations allowed) ----------------
__device__ __align__(16) __half g_Wh[OUT_DIM * IN_DIM];
__device__ unsigned long long g_isum;   // fixed-point global row-sum (deterministic)
__device__ double g_sumb;               // sum of bias (fp64, fixed order)
__device__ int    g_cntf[CMP_BLOCKS];   // count | FLAG, reset by prep_kernel each run

// ---------------- smem layout (dynamic) ----------------
// A: 2 stages x 8KB (64 rows x 128B) ; B: 2 stages x 16KB ; bias
#define SM_A(s)  ((s) * 8192)
#define SM_B(s)  (16384 + (s) * 16384)
#define SM_BIAS  49152
#define SMEM_TOTAL (49152 + 512 + 64)

#define SWZ(o) ((o) ^ (((o) >> 3) & 0x70))
#define FLAGBIT (1 << 30)

__device__ __forceinline__ uint32_t smem_u32(const void* p) {
    uint32_t a;
    asm("{ .reg .u64 t; cvta.to.shared.u64 t, %1; cvt.u32.u64 %0, t; }" : "=r"(a) : "l"(p));
    return a;
}

__device__ __forceinline__ void ldsm4(uint32_t* r, uint32_t addr) {
    asm volatile("ldmatrix.sync.aligned.m8n8.x4.shared.b16 {%0,%1,%2,%3}, [%4];"
        : "=r"(r[0]), "=r"(r[1]), "=r"(r[2]), "=r"(r[3]) : "r"(addr));
}

__device__ __forceinline__ void mma16816(float* d, const uint32_t* a, uint32_t b0, uint32_t b1) {
    asm volatile("mma.sync.aligned.m16n8k16.row.col.f32.f16.f16.f32 "
        "{%0,%1,%2,%3},{%4,%5,%6,%7},{%8,%9},{%0,%1,%2,%3};"
        : "+f"(d[0]), "+f"(d[1]), "+f"(d[2]), "+f"(d[3])
        : "r"(a[0]), "r"(a[1]), "r"(a[2]), "r"(a[3]), "r"(b0), "r"(b1));
}

#define CP_ASYNC16(dst, src) \
    asm volatile("cp.async.cg.shared.global [%0], [%1], 16;" :: "r"(dst), "l"(src) : "memory")
#define CP_COMMIT()  asm volatile("cp.async.commit_group;" ::: "memory")
#define CP_WAIT0()   asm volatile("cp.async.wait_group 0;" ::: "memory")

// ============================================================
// 0a. W -> fp16 (128 blocks x 512)
// ============================================================
__global__ void wsplit_kernel(const float* __restrict__ W) {
    int i = blockIdx.x * 512 + threadIdx.x;   // 65536 W elements
    g_Wh[i] = __float2half_rn(W[i]);
}

// 0b. single-block: bias sum + flag/counter resets
__global__ void prep_kernel(const float* __restrict__ bias) {
    const int tid = threadIdx.x;
    g_cntf[tid] = 0;
    __shared__ double sb[128];
    if (tid < 128) sb[tid] = (double)bias[tid];
    __syncthreads();
    for (int st = 64; st; st >>= 1) {
        if (tid < st) sb[tid] += sb[tid + st];
        __syncthreads();
    }
    if (tid == 0) { g_sumb = sb[0]; g_isum = 0ull; }
}

// ============================================================
// GEMM pipeline helpers (same idiom, 64-row A tile)
// ============================================================
__device__ __forceinline__ void load_W_chunk(uint32_t sb, int s, int k0, int tid) {
    #pragma unroll
    for (int i = 0; i < 4; i++) {
        int l = tid + 256 * i;          // 0..1023
        int row = l >> 3, u = l & 7;
        uint32_t off = SWZ((uint32_t)(row * 128 + u * 16));
        CP_ASYNC16(sb + SM_B(s) + off, g_Wh + row * IN_DIM + k0 + u * 8);
    }
    CP_COMMIT();
}

// 64 rows x 64 cols: 512 16B-units, 2 per thread
__device__ __forceinline__ void ldg_cvt_x(const float* xb, int k0, int tid, uint4* xv) {
    #pragma unroll
    for (int i = 0; i < 2; i++) {
        int l = tid + 256 * i;          // 0..511
        int row = l >> 3, u = l & 7;
        const float* p = xb + (size_t)row * IN_DIM + k0 + u * 8;
        float4 v0 = __ldg((const float4*)p);
        float4 v1 = __ldg((const float4*)(p + 4));
        __half2 ha = __floats2half2_rn(v0.x, v0.y);
        __half2 hb = __floats2half2_rn(v0.z, v0.w);
        __half2 hc = __floats2half2_rn(v1.x, v1.y);
        __half2 hd = __floats2half2_rn(v1.z, v1.w);
        xv[i] = make_uint4(*(uint32_t*)&ha, *(uint32_t*)&hb,
                           *(uint32_t*)&hc, *(uint32_t*)&hd);
    }
}

__device__ __forceinline__ void sts_x(char* smem, int s, int tid, const uint4* xv) {
    #pragma unroll
    for (int i = 0; i < 2; i++) {
        int l = tid + 256 * i;
        int row = l >> 3, u = l & 7;
        *(uint4*)(smem + SM_A(s) + SWZ((uint32_t)(row * 128 + u * 16))) = xv[i];
    }
}

// ============================================================
// 1. HMMA GEMM (fp16), 64x128 CTA tile, 3 CTAs/SM
// ============================================================
__global__ void __launch_bounds__(256, 3) gemm_tc_kernel(
    const float* __restrict__ x, const float* __restrict__ bias,
    float* __restrict__ out, float* __restrict__ idx_out)
{
    extern __shared__ char smem[];
    const uint32_t sb = smem_u32(smem);
    const int tid = threadIdx.x, wid = tid >> 5, lane = tid & 31;
    const int wm = wid & 3, wn = wid >> 2;       // warp tile: 16(M) x 64(N)
    const size_t m0 = (size_t)blockIdx.x * TILE_M;
    const float* xb = x + m0 * IN_DIM;

    // absorb the -1 fill (hidden under prologue LDG latency)
    if (tid < 64) idx_out[blockIdx.x * 64 + tid] = -1.0f;
    if (tid < 128) ((float*)(smem + SM_BIAS))[tid] = bias[tid];

    float acc[8][4];
    #pragma unroll
    for (int nt = 0; nt < 8; nt++)
        #pragma unroll
        for (int j = 0; j < 4; j++) acc[nt][j] = 0.0f;

    // ---- prologue: chunk 0 ----
    uint4 xv[2];
    ldg_cvt_x(xb, 0, tid, xv);
    load_W_chunk(sb, 0, 0, tid);
    CP_WAIT0();
    sts_x(smem, 0, tid, xv);
    __syncthreads();

    const int arow  = lane & 15;
    const int acolb = ((lane >> 4) & 1) * 16;
    const int brow  = (lane & 7) + ((lane >> 4) & 1) * 8;
    const int bcolb = ((lane >> 3) & 1) * 16;

    for (int c = 0; c < 8; c++) {
        const int s = c & 1, ns = s ^ 1;
        if (c < 7) {
            ldg_cvt_x(xb, (c + 1) * 64, tid, xv);
            load_W_chunk(sb, ns, (c + 1) * 64, tid);
        }
        const uint32_t sA = sb + SM_A(s);
        const uint32_t sB = sb + SM_B(s);

        #pragma unroll
        for (int kk = 0; kk < 4; kk++) {
            uint32_t ah[4], bh[4][4];
            ldsm4(ah, sA + SWZ((uint32_t)((16 * wm + arow) * 128 + kk * 32 + acolb)));
            #pragma unroll
            for (int np = 0; np < 4; np++)
                ldsm4(bh[np], sB + SWZ((uint32_t)((64 * wn + 16 * np + brow) * 128 + kk * 32 + bcolb)));
            #pragma unroll
            for (int nt = 0; nt < 8; nt++) {
                const uint32_t* ph = &bh[nt >> 1][(nt & 1) * 2];
                mma16816(acc[nt], ah, ph[0], ph[1]);
            }
        }
        if (c < 7) {
            CP_WAIT0();
            sts_x(smem, ns, tid, xv);
        }
        __syncthreads();
    }

    // ---- epilogue: bias + store + fp32 thread-sum -> per-warp atomic ----
    const float* bs = (const float*)(smem + SM_BIAS);
    float fsum = 0.0f;
    {
        const size_t r0 = m0 + 16 * wm + (lane >> 2);
        #pragma unroll
        for (int nt = 0; nt < 8; nt++) {
            int col = 64 * wn + 8 * nt + 2 * (lane & 3);
            float b0 = bs[col], b1 = bs[col + 1];
            float2 v0 = make_float2(acc[nt][0] + b0, acc[nt][1] + b1);
            float2 v1 = make_float2(acc[nt][2] + b0, acc[nt][3] + b1);
            *(float2*)(out + r0 * OUT_DIM + col)       = v0;
            *(float2*)(out + (r0 + 8) * OUT_DIM + col) = v1;
            fsum += acc[nt][0] + acc[nt][1] + acc[nt][2] + acc[nt][3];
        }
    }
    double dsum = (double)fsum;
    #pragma unroll
    for (int st = 16; st; st >>= 1)
        dsum += __shfl_xor_sync(0xFFFFFFFFu, dsum, st);
    if (lane == 0) {
        long long q = __double2ll_rn(dsum * FIX_SCALE);
        atomicAdd(&g_isum, (unsigned long long)q);   // integer: order-independent
    }
}

// ============================================================
// 2. fused compaction (predecessor-only poll)  [proven]
// ============================================================
__global__ void compact_kernel(const float* __restrict__ mask, float* __restrict__ idx_out) {
    const int tid = threadIdx.x, b = blockIdx.x;
    const int lane = tid & 31, w = tid >> 5;

    const float thr = (float)((double)(long long)g_isum / FIX_SCALE / (double)N_ROWS + g_sumb);

    const int i = b * 512 + tid;
    const int p = mask[i] > thr;
    const unsigned bal = __ballot_sync(0xFFFFFFFFu, p);

    __shared__ int wc[16];
    __shared__ int sred[16];
    if (lane == 0) wc[w] = __popc(bal);
    __syncthreads();

    if (tid == 0) {
        int t = 0;
        #pragma unroll
        for (int ww = 0; ww < 16; ww++) t += wc[ww];
        atomicExch(&g_cntf[b], t | FLAGBIT);
    }

    int mysum = 0;
    if (tid < b) {
        int v;
        do { v = *((volatile int*)&g_cntf[tid]); } while (!(v & FLAGBIT));
        mysum = v & (FLAGBIT - 1);
    }
    #pragma unroll
    for (int st = 16; st; st >>= 1)
        mysum += __shfl_xor_sync(0xFFFFFFFFu, mysum, st);
    if (lane == 0) sred[w] = mysum;
    __syncthreads();

    if (tid == 0) {
        int base = 0;
        #pragma unroll
        for (int ww = 0; ww < 16; ww++) base += sred[ww];
        #pragma unroll
        for (int ww = 0; ww < 16; ww++) { int c2 = wc[ww]; wc[ww] = base; base += c2; }
    }
    __syncthreads();

    if (p) {
        int pos = wc[w] + __popc(bal & ((1u << lane) - 1u));
        idx_out[pos] = (float)i;
    }
}

// ============================================================
// launch
// ============================================================
extern "C" void kernel_launch(void* const* d_in, const int* in_sizes, int n_in,
                              void* d_out, int out_size) {
    const float* x    = (const float*)d_in[0];
    const float* mask = (const float*)d_in[1];
    const float* W    = (const float*)d_in[2];
    const float* b    = (const float*)d_in[3];
    float* out = (float*)d_out;
    float* idx_out = out + (size_t)N_ROWS * OUT_DIM;

    cudaFuncSetAttribute(gemm_tc_kernel, cudaFuncAttributeMaxDynamicSharedMemorySize, SMEM_TOTAL);

    wsplit_kernel<<<128, 512>>>(W);
    prep_kernel<<<1, 512>>>(b);
    gemm_tc_kernel<<<GEMM_BLOCKS, 256, SMEM_TOTAL>>>(x, b, out, idx_out);
    compact_kernel<<<CMP_BLOCKS, 512>>>(mask, idx_out);
}

// round 16
// speedup vs baseline: 1.1638x; 1.1638x over previous
#include <cuda_runtime.h>
#include <cuda_fp16.h>
#include <cstdint>

#define N_ROWS  262144
#define IN_DIM  512
#define OUT_DIM 128
#define GEMM_BLOCKS (N_ROWS / 128)   // 2048
#define CMP_BLOCKS  256              // 1024 elements per block
#define FIX_SCALE 1048576.0          // 2^20

// ---------------- device scratch (no allocations allowed) ----------------
__device__ __align__(16) __half g_Wh[OUT_DIM * IN_DIM];
__device__ unsigned long long g_isum;   // fixed-point global row-sum (deterministic)
__device__ double g_sumb;               // sum of bias (fp64, fixed order)
__device__ int    g_cntf[512];          // count | FLAG, reset by prep_kernel each run

// ---------------- smem layout (dynamic) ----------------
// two stages, each: A 16K | B 16K   (128 rows x 128B, SW128)
#define SM_A(s)  ((s) * 32768 + 0)
#define SM_B(s)  ((s) * 32768 + 16384)
#define SM_BIAS  65536
#define SMEM_TOTAL (65536 + 512 + 64)

#define SWZ(o) ((o) ^ (((o) >> 3) & 0x70))
#define FLAGBIT (1 << 30)

__device__ __forceinline__ uint32_t smem_u32(const void* p) {
    uint32_t a;
    asm("{ .reg .u64 t; cvta.to.shared.u64 t, %1; cvt.u32.u64 %0, t; }" : "=r"(a) : "l"(p));
    return a;
}

__device__ __forceinline__ void ldsm4(uint32_t* r, uint32_t addr) {
    asm volatile("ldmatrix.sync.aligned.m8n8.x4.shared.b16 {%0,%1,%2,%3}, [%4];"
        : "=r"(r[0]), "=r"(r[1]), "=r"(r[2]), "=r"(r[3]) : "r"(addr));
}

__device__ __forceinline__ void mma16816(float* d, const uint32_t* a, uint32_t b0, uint32_t b1) {
    asm volatile("mma.sync.aligned.m16n8k16.row.col.f32.f16.f16.f32 "
        "{%0,%1,%2,%3},{%4,%5,%6,%7},{%8,%9},{%0,%1,%2,%3};"
        : "+f"(d[0]), "+f"(d[1]), "+f"(d[2]), "+f"(d[3])
        : "r"(a[0]), "r"(a[1]), "r"(a[2]), "r"(a[3]), "r"(b0), "r"(b1));
}

#define CP_ASYNC16(dst, src) \
    asm volatile("cp.async.cg.shared.global [%0], [%1], 16;" :: "r"(dst), "l"(src) : "memory")
#define CP_COMMIT()  asm volatile("cp.async.commit_group;" ::: "memory")
#define CP_WAIT0()   asm volatile("cp.async.wait_group 0;" ::: "memory")

// ============================================================
// 0a. W -> fp16 (128 blocks x 512)
// ============================================================
__global__ void wsplit_kernel(const float* __restrict__ W) {
    int i = blockIdx.x * 512 + threadIdx.x;   // 65536 W elements
    g_Wh[i] = __float2half_rn(W[i]);
}

// 0b. single-block: bias sum + flag/counter resets
__global__ void prep_kernel(const float* __restrict__ bias) {
    const int tid = threadIdx.x;
    g_cntf[tid] = 0;
    __shared__ double sb[128];
    if (tid < 128) sb[tid] = (double)bias[tid];
    __syncthreads();
    for (int st = 64; st; st >>= 1) {
        if (tid < st) sb[tid] += sb[tid + st];
        __syncthreads();
    }
    if (tid == 0) { g_sumb = sb[0]; g_isum = 0ull; }
}

// ============================================================
// GEMM pipeline helpers (proven round-10/14 shape, unchanged)
// ============================================================
__device__ __forceinline__ void load_W_chunk(uint32_t sb, int s, int k0, int tid) {
    #pragma unroll
    for (int i = 0; i < 4; i++) {
        int l = tid + 256 * i;          // 0..1023
        int row = l >> 3, u = l & 7;
        uint32_t off = SWZ((uint32_t)(row * 128 + u * 16));
        CP_ASYNC16(sb + SM_B(s) + off, g_Wh + row * IN_DIM + k0 + u * 8);
    }
    CP_COMMIT();
}

__device__ __forceinline__ void ldg_cvt_x(const float* xb, int k0, int tid, uint4* xv) {
    #pragma unroll
    for (int i = 0; i < 4; i++) {
        int l = tid + 256 * i;          // 0..1023
        int row = l >> 3, u = l & 7;
        const float* p = xb + (size_t)row * IN_DIM + k0 + u * 8;
        float4 v0 = __ldg((const float4*)p);
        float4 v1 = __ldg((const float4*)(p + 4));
        __half2 ha = __floats2half2_rn(v0.x, v0.y);
        __half2 hb = __floats2half2_rn(v0.z, v0.w);
        __half2 hc = __floats2half2_rn(v1.x, v1.y);
        __half2 hd = __floats2half2_rn(v1.z, v1.w);
        xv[i] = make_uint4(*(uint32_t*)&ha, *(uint32_t*)&hb,
                           *(uint32_t*)&hc, *(uint32_t*)&hd);
    }
}

__device__ __forceinline__ void sts_x(char* smem, int s, int tid, const uint4* xv) {
    #pragma unroll
    for (int i = 0; i < 4; i++) {
        int l = tid + 256 * i;
        int row = l >> 3, u = l & 7;
        *(uint4*)(smem + SM_A(s) + SWZ((uint32_t)(row * 128 + u * 16))) = xv[i];
    }
}

// ============================================================
// 1. HMMA GEMM (fp16) — byte-identical to round-14
// ============================================================
__global__ void __launch_bounds__(256, 2) gemm_tc_kernel(
    const float* __restrict__ x, const float* __restrict__ bias,
    float* __restrict__ out, float* __restrict__ idx_out)
{
    extern __shared__ char smem[];
    const uint32_t sb = smem_u32(smem);
    const int tid = threadIdx.x, wid = tid >> 5, lane = tid & 31;
    const int wm = wid & 3, wn = wid >> 2;       // warp tile: 32(M) x 64(N)
    const size_t m0 = (size_t)blockIdx.x * 128;
    const float* xb = x + m0 * IN_DIM;

    // absorb the -1 fill (hidden under prologue LDG latency)
    if (tid < 128) idx_out[blockIdx.x * 128 + tid] = -1.0f;
    if (tid < 128) ((float*)(smem + SM_BIAS))[tid] = bias[tid];

    float acc[2][8][4];
    #pragma unroll
    for (int mt = 0; mt < 2; mt++)
        #pragma unroll
        for (int nt = 0; nt < 8; nt++)
            #pragma unroll
            for (int j = 0; j < 4; j++) acc[mt][nt][j] = 0.0f;

    // ---- prologue: chunk 0 ----
    uint4 xv[4];
    ldg_cvt_x(xb, 0, tid, xv);
    load_W_chunk(sb, 0, 0, tid);
    CP_WAIT0();
    sts_x(smem, 0, tid, xv);
    __syncthreads();

    const int arow  = lane & 15;
    const int acolb = ((lane >> 4) & 1) * 16;
    const int brow  = (lane & 7) + ((lane >> 4) & 1) * 8;
    const int bcolb = ((lane >> 3) & 1) * 16;

    for (int c = 0; c < 8; c++) {
        const int s = c & 1, ns = s ^ 1;
        if (c < 7) {
            ldg_cvt_x(xb, (c + 1) * 64, tid, xv);
            load_W_chunk(sb, ns, (c + 1) * 64, tid);
        }
        const uint32_t sA = sb + SM_A(s);
        const uint32_t sB = sb + SM_B(s);

        #pragma unroll
        for (int kk = 0; kk < 4; kk++) {
            uint32_t ah[2][4], bh[4][4];
            #pragma unroll
            for (int mt = 0; mt < 2; mt++)
                ldsm4(ah[mt], sA + SWZ((uint32_t)((32 * wm + 16 * mt + arow) * 128 + kk * 32 + acolb)));
            #pragma unroll
            for (int np = 0; np < 4; np++)
                ldsm4(bh[np], sB + SWZ((uint32_t)((64 * wn + 16 * np + brow) * 128 + kk * 32 + bcolb)));
            #pragma unroll
            for (int mt = 0; mt < 2; mt++)
                #pragma unroll
                for (int nt = 0; nt < 8; nt++) {
                    const uint32_t* ph = &bh[nt >> 1][(nt & 1) * 2];
                    mma16816(acc[mt][nt], ah[mt], ph[0], ph[1]);
                }
        }
        if (c < 7) {
            CP_WAIT0();
            sts_x(smem, ns, tid, xv);
        }
        __syncthreads();
    }

    // ---- epilogue: bias + store + fp32 thread-sum -> per-warp atomic ----
    const float* bs = (const float*)(smem + SM_BIAS);
    float fsum = 0.0f;
    #pragma unroll
    for (int mt = 0; mt < 2; mt++) {
        const size_t r0 = m0 + 32 * wm + 16 * mt + (lane >> 2);
        #pragma unroll
        for (int nt = 0; nt < 8; nt++) {
            int col = 64 * wn + 8 * nt + 2 * (lane & 3);
            float b0 = bs[col], b1 = bs[col + 1];
            float2 v0 = make_float2(acc[mt][nt][0] + b0, acc[mt][nt][1] + b1);
            float2 v1 = make_float2(acc[mt][nt][2] + b0, acc[mt][nt][3] + b1);
            *(float2*)(out + r0 * OUT_DIM + col)       = v0;
            *(float2*)(out + (r0 + 8) * OUT_DIM + col) = v1;
            fsum += acc[mt][nt][0] + acc[mt][nt][1]
                  + acc[mt][nt][2] + acc[mt][nt][3];
        }
    }
    double dsum = (double)fsum;
    #pragma unroll
    for (int st = 16; st; st >>= 1)
        dsum += __shfl_xor_sync(0xFFFFFFFFu, dsum, st);
    if (lane == 0) {
        long long q = __double2ll_rn(dsum * FIX_SCALE);
        atomicAdd(&g_isum, (unsigned long long)q);   // integer: order-independent
    }
}

// ============================================================
// 2. fused compaction: 256 blocks x 1024 elements (2/thread)
//    segments [b*1024, +512) then [+512, +1024) keep order
// ============================================================
__global__ void compact_kernel(const float* __restrict__ mask, float* __restrict__ idx_out) {
    const int tid = threadIdx.x, b = blockIdx.x;
    const int lane = tid & 31, w = tid >> 5;

    const float thr = (float)((double)(long long)g_isum / FIX_SCALE / (double)N_ROWS + g_sumb);

    const int i0 = b * 1024 + tid;
    const int i1 = i0 + 512;
    const int p0 = mask[i0] > thr;
    const int p1 = mask[i1] > thr;
    const unsigned bal0 = __ballot_sync(0xFFFFFFFFu, p0);
    const unsigned bal1 = __ballot_sync(0xFFFFFFFFu, p1);

    __shared__ int wc[32];     // counts in position order: seg0 warps, then seg1 warps
    __shared__ int sred[16];
    if (lane == 0) { wc[w] = __popc(bal0); wc[16 + w] = __popc(bal1); }
    __syncthreads();

    if (tid == 0) {
        int t = 0;
        #pragma unroll
        for (int ww = 0; ww < 32; ww++) t += wc[ww];
        atomicExch(&g_cntf[b], t | FLAGBIT);
    }

    // predecessor poll: thread j (< b) waits for block j's count
    int mysum = 0;
    if (tid < b) {
        int v;
        do { v = *((volatile int*)&g_cntf[tid]); } while (!(v & FLAGBIT));
        mysum = v & (FLAGBIT - 1);
    }
    #pragma unroll
    for (int st = 16; st; st >>= 1)
        mysum += __shfl_xor_sync(0xFFFFFFFFu, mysum, st);
    if (lane == 0) sred[w] = mysum;
    __syncthreads();

    if (tid == 0) {
        int base = 0;
        #pragma unroll
        for (int ww = 0; ww < 16; ww++) base += sred[ww];
        #pragma unroll
        for (int ww = 0; ww < 32; ww++) { int c2 = wc[ww]; wc[ww] = base; base += c2; }
    }
    __syncthreads();

    if (p0) {
        int pos = wc[w] + __popc(bal0 & ((1u << lane) - 1u));
        idx_out[pos] = (float)i0;
    }
    if (p1) {
        int pos = wc[16 + w] + __popc(bal1 & ((1u << lane) - 1u));
        idx_out[pos] = (float)i1;
    }
}

// ============================================================
// launch
// ============================================================
extern "C" void kernel_launch(void* const* d_in, const int* in_sizes, int n_in,
                              void* d_out, int out_size) {
    const float* x    = (const float*)d_in[0];
    const float* mask = (const float*)d_in[1];
    const float* W    = (const float*)d_in[2];
    const float* b    = (const float*)d_in[3];
    float* out = (float*)d_out;
    float* idx_out = out + (size_t)N_ROWS * OUT_DIM;

    cudaFuncSetAttribute(gemm_tc_kernel, cudaFuncAttributeMaxDynamicSharedMemorySize, SMEM_TOTAL);

    wsplit_kernel<<<128, 512>>>(W);
    prep_kernel<<<1, 512>>>(b);
    gemm_tc_kernel<<<GEMM_BLOCKS, 256, SMEM_TOTAL>>>(x, b, out, idx_out);
    compact_kernel<<<CMP_BLOCKS, 512>>>(mask, idx_out);
}

// round 17
// speedup vs baseline: 1.1790x; 1.0131x over previous
#include <cuda_runtime.h>
#include <cuda_fp16.h>
#include <cstdint>

#define N_ROWS  262144
#define IN_DIM  512
#define OUT_DIM 128
#define GEMM_BLOCKS (N_ROWS / 128)   // 2048
#define CMP_BLOCKS  128              // 2048 elements per block (4/thread)
#define FIX_SCALE 1048576.0          // 2^20

// ---------------- device scratch (no allocations allowed) ----------------
__device__ __align__(16) __half g_Wh[OUT_DIM * IN_DIM];
__device__ unsigned long long g_isum;   // fixed-point global row-sum (deterministic)
__device__ double g_sumb;               // sum of bias (fp64, fixed order)
__device__ int    g_cntf[512];          // count | FLAG, reset by prep_kernel each run

// ---------------- smem layout (dynamic) ----------------
// two stages, each: A 16K | B 16K   (128 rows x 128B, SW128)
#define SM_A(s)  ((s) * 32768 + 0)
#define SM_B(s)  ((s) * 32768 + 16384)
#define SM_BIAS  65536
#define SMEM_TOTAL (65536 + 512 + 64)

#define SWZ(o) ((o) ^ (((o) >> 3) & 0x70))
#define FLAGBIT (1 << 30)

__device__ __forceinline__ uint32_t smem_u32(const void* p) {
    uint32_t a;
    asm("{ .reg .u64 t; cvta.to.shared.u64 t, %1; cvt.u32.u64 %0, t; }" : "=r"(a) : "l"(p));
    return a;
}

__device__ __forceinline__ void ldsm4(uint32_t* r, uint32_t addr) {
    asm volatile("ldmatrix.sync.aligned.m8n8.x4.shared.b16 {%0,%1,%2,%3}, [%4];"
        : "=r"(r[0]), "=r"(r[1]), "=r"(r[2]), "=r"(r[3]) : "r"(addr));
}

__device__ __forceinline__ void mma16816(float* d, const uint32_t* a, uint32_t b0, uint32_t b1) {
    asm volatile("mma.sync.aligned.m16n8k16.row.col.f32.f16.f16.f32 "
        "{%0,%1,%2,%3},{%4,%5,%6,%7},{%8,%9},{%0,%1,%2,%3};"
        : "+f"(d[0]), "+f"(d[1]), "+f"(d[2]), "+f"(d[3])
        : "r"(a[0]), "r"(a[1]), "r"(a[2]), "r"(a[3]), "r"(b0), "r"(b1));
}

#define CP_ASYNC16(dst, src) \
    asm volatile("cp.async.cg.shared.global [%0], [%1], 16;" :: "r"(dst), "l"(src) : "memory")
#define CP_COMMIT()  asm volatile("cp.async.commit_group;" ::: "memory")
#define CP_WAIT0()   asm volatile("cp.async.wait_group 0;" ::: "memory")

// ============================================================
// 0. prep: blocks 0..15 convert W (vectorized, 8 elems/thread);
//    block 16: bias sum + flag/counter resets
// ============================================================
__global__ void prep_kernel(const float* __restrict__ W, const float* __restrict__ bias) {
    const int b = blockIdx.x, tid = threadIdx.x;
    if (b < 16) {
        int base = (b * 512 + tid) * 8;     // 65536 elems / 8 per thread
        float4 v0 = __ldg((const float4*)(W + base));
        float4 v1 = __ldg((const float4*)(W + base + 4));
        __half2 ha = __floats2half2_rn(v0.x, v0.y);
        __half2 hb = __floats2half2_rn(v0.z, v0.w);
        __half2 hc = __floats2half2_rn(v1.x, v1.y);
        __half2 hd = __floats2half2_rn(v1.z, v1.w);
        uint4 pk = make_uint4(*(uint32_t*)&ha, *(uint32_t*)&hb,
                              *(uint32_t*)&hc, *(uint32_t*)&hd);
        *(uint4*)(g_Wh + base) = pk;
    } else {
        g_cntf[tid] = 0;
        __shared__ double sb[128];
        if (tid < 128) sb[tid] = (double)bias[tid];
        __syncthreads();
        for (int st = 64; st; st >>= 1) {
            if (tid < st) sb[tid] += sb[tid + st];
            __syncthreads();
        }
        if (tid == 0) { g_sumb = sb[0]; g_isum = 0ull; }
    }
}

// ============================================================
// GEMM pipeline helpers (proven round-10/14 shape, unchanged)
// ============================================================
__device__ __forceinline__ void load_W_chunk(uint32_t sb, int s, int k0, int tid) {
    #pragma unroll
    for (int i = 0; i < 4; i++) {
        int l = tid + 256 * i;          // 0..1023
        int row = l >> 3, u = l & 7;
        uint32_t off = SWZ((uint32_t)(row * 128 + u * 16));
        CP_ASYNC16(sb + SM_B(s) + off, g_Wh + row * IN_DIM + k0 + u * 8);
    }
    CP_COMMIT();
}

__device__ __forceinline__ void ldg_cvt_x(const float* xb, int k0, int tid, uint4* xv) {
    #pragma unroll
    for (int i = 0; i < 4; i++) {
        int l = tid + 256 * i;          // 0..1023
        int row = l >> 3, u = l & 7;
        const float* p = xb + (size_t)row * IN_DIM + k0 + u * 8;
        float4 v0 = __ldg((const float4*)p);
        float4 v1 = __ldg((const float4*)(p + 4));
        __half2 ha = __floats2half2_rn(v0.x, v0.y);
        __half2 hb = __floats2half2_rn(v0.z, v0.w);
        __half2 hc = __floats2half2_rn(v1.x, v1.y);
        __half2 hd = __floats2half2_rn(v1.z, v1.w);
        xv[i] = make_uint4(*(uint32_t*)&ha, *(uint32_t*)&hb,
                           *(uint32_t*)&hc, *(uint32_t*)&hd);
    }
}

__device__ __forceinline__ void sts_x(char* smem, int s, int tid, const uint4* xv) {
    #pragma unroll
    for (int i = 0; i < 4; i++) {
        int l = tid + 256 * i;
        int row = l >> 3, u = l & 7;
        *(uint4*)(smem + SM_A(s) + SWZ((uint32_t)(row * 128 + u * 16))) = xv[i];
    }
}

// ============================================================
// 1. HMMA GEMM (fp16) — byte-identical to round-14
// ============================================================
__global__ void __launch_bounds__(256, 2) gemm_tc_kernel(
    const float* __restrict__ x, const float* __restrict__ bias,
    float* __restrict__ out, float* __restrict__ idx_out)
{
    extern __shared__ char smem[];
    const uint32_t sb = smem_u32(smem);
    const int tid = threadIdx.x, wid = tid >> 5, lane = tid & 31;
    const int wm = wid & 3, wn = wid >> 2;       // warp tile: 32(M) x 64(N)
    const size_t m0 = (size_t)blockIdx.x * 128;
    const float* xb = x + m0 * IN_DIM;

    // absorb the -1 fill (hidden under prologue LDG latency)
    if (tid < 128) idx_out[blockIdx.x * 128 + tid] = -1.0f;
    if (tid < 128) ((float*)(smem + SM_BIAS))[tid] = bias[tid];

    float acc[2][8][4];
    #pragma unroll
    for (int mt = 0; mt < 2; mt++)
        #pragma unroll
        for (int nt = 0; nt < 8; nt++)
            #pragma unroll
            for (int j = 0; j < 4; j++) acc[mt][nt][j] = 0.0f;

    // ---- prologue: chunk 0 ----
    uint4 xv[4];
    ldg_cvt_x(xb, 0, tid, xv);
    load_W_chunk(sb, 0, 0, tid);
    CP_WAIT0();
    sts_x(smem, 0, tid, xv);
    __syncthreads();

    const int arow  = lane & 15;
    const int acolb = ((lane >> 4) & 1) * 16;
    const int brow  = (lane & 7) + ((lane >> 4) & 1) * 8;
    const int bcolb = ((lane >> 3) & 1) * 16;

    for (int c = 0; c < 8; c++) {
        const int s = c & 1, ns = s ^ 1;
        if (c < 7) {
            ldg_cvt_x(xb, (c + 1) * 64, tid, xv);
            load_W_chunk(sb, ns, (c + 1) * 64, tid);
        }
        const uint32_t sA = sb + SM_A(s);
        const uint32_t sB = sb + SM_B(s);

        #pragma unroll
        for (int kk = 0; kk < 4; kk++) {
            uint32_t ah[2][4], bh[4][4];
            #pragma unroll
            for (int mt = 0; mt < 2; mt++)
                ldsm4(ah[mt], sA + SWZ((uint32_t)((32 * wm + 16 * mt + arow) * 128 + kk * 32 + acolb)));
            #pragma unroll
            for (int np = 0; np < 4; np++)
                ldsm4(bh[np], sB + SWZ((uint32_t)((64 * wn + 16 * np + brow) * 128 + kk * 32 + bcolb)));
            #pragma unroll
            for (int mt = 0; mt < 2; mt++)
                #pragma unroll
                for (int nt = 0; nt < 8; nt++) {
                    const uint32_t* ph = &bh[nt >> 1][(nt & 1) * 2];
                    mma16816(acc[mt][nt], ah[mt], ph[0], ph[1]);
                }
        }
        if (c < 7) {
            CP_WAIT0();
            sts_x(smem, ns, tid, xv);
        }
        __syncthreads();
    }

    // ---- epilogue: bias + store + fp32 thread-sum -> per-warp atomic ----
    const float* bs = (const float*)(smem + SM_BIAS);
    float fsum = 0.0f;
    #pragma unroll
    for (int mt = 0; mt < 2; mt++) {
        const size_t r0 = m0 + 32 * wm + 16 * mt + (lane >> 2);
        #pragma unroll
        for (int nt = 0; nt < 8; nt++) {
            int col = 64 * wn + 8 * nt + 2 * (lane & 3);
            float b0 = bs[col], b1 = bs[col + 1];
            float2 v0 = make_float2(acc[mt][nt][0] + b0, acc[mt][nt][1] + b1);
            float2 v1 = make_float2(acc[mt][nt][2] + b0, acc[mt][nt][3] + b1);
            *(float2*)(out + r0 * OUT_DIM + col)       = v0;
            *(float2*)(out + (r0 + 8) * OUT_DIM + col) = v1;
            fsum += acc[mt][nt][0] + acc[mt][nt][1]
                  + acc[mt][nt][2] + acc[mt][nt][3];
        }
    }
    double dsum = (double)fsum;
    #pragma unroll
    for (int st = 16; st; st >>= 1)
        dsum += __shfl_xor_sync(0xFFFFFFFFu, dsum, st);
    if (lane == 0) {
        long long q = __double2ll_rn(dsum * FIX_SCALE);
        atomicAdd(&g_isum, (unsigned long long)q);   // integer: order-independent
    }
}

// ============================================================
// 2. fused compaction: 128 blocks x 2048 elements (4/thread)
//    segments [b*2048 + k*512, +512), k=0..3, keep order
// ============================================================
__global__ void compact_kernel(const float* __restrict__ mask, float* __restrict__ idx_out) {
    const int tid = threadIdx.x, b = blockIdx.x;
    const int lane = tid & 31, w = tid >> 5;

    const float thr = (float)((double)(long long)g_isum / FIX_SCALE / (double)N_ROWS + g_sumb);

    int pk[4];
    unsigned bal[4];
    #pragma unroll
    for (int k = 0; k < 4; k++) {
        pk[k] = mask[b * 2048 + k * 512 + tid] > thr;
        bal[k] = __ballot_sync(0xFFFFFFFFu, pk[k]);
    }

    __shared__ int wc[64];     // position-ordered: segment k, warp w -> wc[k*16+w]
    __shared__ int sred[16];
    if (lane == 0) {
        #pragma unroll
        for (int k = 0; k < 4; k++) wc[k * 16 + w] = __popc(bal[k]);
    }
    __syncthreads();

    if (tid == 0) {
        int t = 0;
        #pragma unroll
        for (int ww = 0; ww < 64; ww++) t += wc[ww];
        atomicExch(&g_cntf[b], t | FLAGBIT);
    }

    // predecessor poll: thread j (< b) waits for block j's count
    int mysum = 0;
    if (tid < b) {
        int v;
        do { v = *((volatile int*)&g_cntf[tid]); } while (!(v & FLAGBIT));
        mysum = v & (FLAGBIT - 1);
    }
    #pragma unroll
    for (int st = 16; st; st >>= 1)
        mysum += __shfl_xor_sync(0xFFFFFFFFu, mysum, st);
    if (lane == 0) sred[w] = mysum;
    __syncthreads();

    if (tid == 0) {
        int base = 0;
        #pragma unroll
        for (int ww = 0; ww < 16; ww++) base += sred[ww];
        #pragma unroll
        for (int ww = 0; ww < 64; ww++) { int c2 = wc[ww]; wc[ww] = base; base += c2; }
    }
    __syncthreads();

    #pragma unroll
    for (int k = 0; k < 4; k++) {
        if (pk[k]) {
            int pos = wc[k * 16 + w] + __popc(bal[k] & ((1u << lane) - 1u));
            idx_out[pos] = (float)(b * 2048 + k * 512 + tid);
        }
    }
}

// ============================================================
// launch
// ============================================================
extern "C" void kernel_launch(void* const* d_in, const int* in_sizes, int n_in,
                              void* d_out, int out_size) {
    const float* x    = (const float*)d_in[0];
    const float* mask = (const float*)d_in[1];
    const float* W    = (const float*)d_in[2];
    const float* b    = (const float*)d_in[3];
    float* out = (float*)d_out;
    float* idx_out = out + (size_t)N_ROWS * OUT_DIM;

    cudaFuncSetAttribute(gemm_tc_kernel, cudaFuncAttributeMaxDynamicSharedMemorySize, SMEM_TOTAL);

    prep_kernel<<<17, 512>>>(W, b);
    gemm_tc_kernel<<<GEMM_BLOCKS, 256, SMEM_TOTAL>>>(x, b, out, idx_out);
    compact_kernel<<<CMP_BLOCKS, 512>>>(mask, idx_out);
}